// round 17
// baseline (speedup 1.0000x reference)
#include <cuda_runtime.h>

#define NN 64
#define MM 8
#define GG 64
#define GH (GG * GG)        /* 4096 */

#define GH_TILE 16
#define N_TILE 16           /* 2 n per thread, 8 n-slots */
#define NTHREADS 128
#define SB_STRIDE 20        /* floats; 16B-aligned LDS.128 rows */

// ---------------------------------------------------------------------------
__device__ __forceinline__ float det4x4(const float* m) {
    float s0 = m[0]*m[5] - m[1]*m[4];
    float s1 = m[0]*m[6] - m[2]*m[4];
    float s2 = m[0]*m[7] - m[3]*m[4];
    float s3 = m[1]*m[6] - m[2]*m[5];
    float s4 = m[1]*m[7] - m[3]*m[5];
    float s5 = m[2]*m[7] - m[3]*m[6];
    float c5 = m[10]*m[15] - m[11]*m[14];
    float c4 = m[ 9]*m[15] - m[11]*m[13];
    float c3 = m[ 9]*m[14] - m[10]*m[13];
    float c2 = m[ 8]*m[15] - m[11]*m[12];
    float c1 = m[ 8]*m[14] - m[10]*m[12];
    float c0 = m[ 8]*m[13] - m[ 9]*m[12];
    return s0*c5 - s1*c4 + s2*c3 + s3*c2 - s4*c1 + s5*c0;
}

// General adjugate via factored 2x2 minors; returns det.
__device__ __forceinline__ float adj4x4(const float* m, float* b) {
    float s0 = m[0]*m[5] - m[1]*m[4];
    float s1 = m[0]*m[6] - m[2]*m[4];
    float s2 = m[0]*m[7] - m[3]*m[4];
    float s3 = m[1]*m[6] - m[2]*m[5];
    float s4 = m[1]*m[7] - m[3]*m[5];
    float s5 = m[2]*m[7] - m[3]*m[6];
    float c5 = m[10]*m[15] - m[11]*m[14];
    float c4 = m[ 9]*m[15] - m[11]*m[13];
    float c3 = m[ 9]*m[14] - m[10]*m[13];
    float c2 = m[ 8]*m[15] - m[11]*m[12];
    float c1 = m[ 8]*m[14] - m[10]*m[12];
    float c0 = m[ 8]*m[13] - m[ 9]*m[12];
    float det = s0*c5 - s1*c4 + s2*c3 + s3*c2 - s4*c1 + s5*c0;

    b[0]  =  m[5]*c5 - m[6]*c4 + m[7]*c3;
    b[1]  = -m[1]*c5 + m[2]*c4 - m[3]*c3;
    b[2]  =  m[13]*s5 - m[14]*s4 + m[15]*s3;
    b[3]  = -m[ 9]*s5 + m[10]*s4 - m[11]*s3;
    b[4]  = -m[4]*c5 + m[6]*c2 - m[7]*c1;
    b[5]  =  m[0]*c5 - m[2]*c2 + m[3]*c1;
    b[6]  = -m[12]*s5 + m[14]*s2 - m[15]*s1;
    b[7]  =  m[ 8]*s5 - m[10]*s2 + m[11]*s1;
    b[8]  =  m[4]*c4 - m[5]*c2 + m[7]*c0;
    b[9]  = -m[0]*c4 + m[1]*c2 - m[3]*c0;
    b[10] =  m[12]*s4 - m[13]*s2 + m[15]*s0;
    b[11] = -m[ 8]*s4 + m[ 9]*s2 - m[11]*s0;
    b[12] = -m[4]*c3 + m[5]*c1 - m[6]*c0;
    b[13] =  m[0]*c3 - m[1]*c1 + m[2]*c0;
    b[14] = -m[12]*s3 + m[13]*s1 - m[14]*s0;
    b[15] =  m[ 8]*s3 - m[ 9]*s1 + m[10]*s0;
    return det;
}

// Symmetric adjugate: input m symmetric -> adj symmetric; compute 10 entries.
// Output a[10] in order: a00 a01 a02 a03 a11 a12 a13 a22 a23 a33. Returns det.
__device__ __forceinline__ float adj4x4_sym(const float* m, float* a) {
    float s0 = m[0]*m[5] - m[1]*m[4];
    float s1 = m[0]*m[6] - m[2]*m[4];
    float s2 = m[0]*m[7] - m[3]*m[4];
    float s3 = m[1]*m[6] - m[2]*m[5];
    float s4 = m[1]*m[7] - m[3]*m[5];
    float s5 = m[2]*m[7] - m[3]*m[6];
    float c5 = m[10]*m[15] - m[11]*m[14];
    float c4 = m[ 9]*m[15] - m[11]*m[13];
    float c3 = m[ 9]*m[14] - m[10]*m[13];
    float c2 = m[ 8]*m[15] - m[11]*m[12];
    float c1 = m[ 8]*m[14] - m[10]*m[12];
    float c0 = m[ 8]*m[13] - m[ 9]*m[12];

    a[0] =  m[5]*c5 - m[6]*c4 + m[7]*c3;              // a00
    a[1] = -m[1]*c5 + m[2]*c4 - m[3]*c3;              // a01
    a[2] =  m[13]*s5 - m[14]*s4 + m[15]*s3;           // a02
    a[3] = -m[ 9]*s5 + m[10]*s4 - m[11]*s3;           // a03
    a[4] =  m[0]*c5 - m[2]*c2 + m[3]*c1;              // a11
    a[5] = -m[12]*s5 + m[14]*s2 - m[15]*s1;           // a12
    a[6] =  m[ 8]*s5 - m[10]*s2 + m[11]*s1;           // a13
    a[7] =  m[12]*s4 - m[13]*s2 + m[15]*s0;           // a22
    a[8] = -m[ 8]*s4 + m[ 9]*s2 - m[11]*s0;           // a23
    a[9] =  m[ 8]*s3 - m[ 9]*s1 + m[10]*s0;           // a33
    // det via first-row cofactor expansion (adj symmetric)
    return m[0]*a[0] + m[1]*a[1] + m[2]*a[2] + m[3]*a[3];
}

// symmetric 4x4 row access from packed-10
#define SYM(a, r, c) ((r)==0 ? ((c)==0?(a)[0]:(c)==1?(a)[1]:(c)==2?(a)[2]:(a)[3]) : \
                      (r)==1 ? ((c)==0?(a)[1]:(c)==1?(a)[4]:(c)==2?(a)[5]:(a)[6]) : \
                      (r)==2 ? ((c)==0?(a)[2]:(c)==1?(a)[5]:(c)==2?(a)[7]:(a)[8]) : \
                               ((c)==0?(a)[3]:(c)==1?(a)[6]:(c)==2?(a)[8]:(a)[9]))

__device__ __forceinline__ void load16(const float* g, float* r) {
    const float4* p = (const float4*)g;
#pragma unroll
    for (int k = 0; k < 4; k++) {
        float4 v = p[k];
        r[4*k+0] = v.x; r[4*k+1] = v.y; r[4*k+2] = v.z; r[4*k+3] = v.w;
    }
}

struct APack {
    float Cd[4], Co[6], p[4], nca;
};

// Streaming-row apack (low live set); two independent logs for nca.
__device__ __forceinline__ void compute_apack(
    const float* __restrict__ mu_a, const float* __restrict__ sigma_a,
    const float* __restrict__ omega_a, int t, APack& A)
{
    float oa[16], sa[16], adj[16];
    load16(omega_a + (size_t)t * 16, oa);
    load16(sigma_a + (size_t)t * 16, sa);
    float4 mav = ((const float4*)mu_a)[t];
    float ma[4] = {mav.x, mav.y, mav.z, mav.w};

    float detOa = adj4x4(oa, adj);
    float rd = __frcp_rn(detOa);
    float detSa = det4x4(sa);
    // nca = -(log detSa - 2 log|detOa|) : two independent LG2s, no divide
    A.nca = 2.0f * __logf(fabsf(detOa)) - __logf(detSa);

    float q[4];
#pragma unroll
    for (int i = 0; i < 4; i++) {
        float s = 0.f;
#pragma unroll
        for (int j = 0; j < 4; j++) s = fmaf(adj[4*i+j], ma[j], s);
        q[i] = s;
    }

    float rd2 = rd * rd;
    int oi = 0;
#pragma unroll
    for (int i = 0; i < 4; i++) {
        float Ui[4];
#pragma unroll
        for (int k = 0; k < 4; k++) {
            float s = 0.f;
#pragma unroll
            for (int j = 0; j < 4; j++) s = fmaf(adj[4*i+j], sa[4*j+k], s);
            Ui[k] = s;
        }
        float s = 0.f;
#pragma unroll
        for (int k = 0; k < 4; k++) s = fmaf(Ui[k], adj[4*i+k], s);
        A.Cd[i] = fmaf(q[i], q[i], s) * rd2;
#pragma unroll
        for (int j = 0; j < 4; j++) {
            if (j > i) {
                float s2 = 0.f;
#pragma unroll
                for (int k = 0; k < 4; k++) s2 = fmaf(Ui[k], adj[4*j+k], s2);
                A.Co[oi++] = fmaf(q[i], q[j], s2) * rd2;
            }
        }
    }
#pragma unroll
    for (int i = 0; i < 4; i++) A.p[i] = q[i] * rd;
}

__device__ __forceinline__ float fast_tanh(float x) {
    float r;
    asm("tanh.approx.f32 %0, %1;" : "=f"(r) : "f"(x));
    return r;
}

// ---------------------------------------------------------------------------
// Fused kernel, 128 threads/block, grid (256, 4). 72-reg cap via (128,7).
// Phase 1: symmetric-adjugate b-payload into smem.
// Phase 2: 2 n per thread; 8-m loop, split accumulators + tanh sigmoid.
// ---------------------------------------------------------------------------
__global__ void __launch_bounds__(NTHREADS, 7) species_fused_kernel(
    const float* __restrict__ mu_a, const float* __restrict__ sigma_a,
    const float* __restrict__ omega_a, const float* __restrict__ mu_b,
    const float* __restrict__ sigma_b, const float* __restrict__ omega_b,
    const float* __restrict__ chi, float* __restrict__ out)
{
    __shared__ float sbuf[MM * GH_TILE * SB_STRIDE];   // 10 KB

    int tid = threadIdx.x;
    int gh0 = blockIdx.x * GH_TILE;
    int n0  = blockIdx.y * N_TILE;

    // ---- phase 1: per-b payload into smem ----
    {
        int m = tid >> 4;
        int g = tid & 15;
        int bi = m * GH + gh0 + g;

        float sb[16], ob[16], aS[10];
        load16(sigma_b + (size_t)bi * 16, sb);
        load16(omega_b + (size_t)bi * 16, ob);
        float4 mbv = ((const float4*)mu_b)[bi];
        float mb[4] = {mbv.x, mbv.y, mbv.z, mbv.w};

        float detSb = adj4x4_sym(sb, aS);
        float rs = __frcp_rn(detSb);
        float detOb = det4x4(ob);
        // cb = log detSb - 2 log|detOb| : two independent LG2s
        float cb = __logf(detSb) - 2.0f * __logf(fabsf(detOb));

        // E = Ob^T * (adjS * Ob), streamed column-by-column of T = adjS*Ob.
        // Upper-tri order: (0,1)=0 (0,2)=1 (0,3)=2 (1,2)=3 (1,3)=4 (2,3)=5
        float Ed[4], Eo[6];
        float rs2 = 2.0f * rs;
#pragma unroll
        for (int c = 0; c < 4; c++) {
            float Tc[4];
#pragma unroll
            for (int k = 0; k < 4; k++) {
                float s = 0.f;
#pragma unroll
                for (int j = 0; j < 4; j++) s = fmaf(SYM(aS, k, j), ob[4*j+c], s);
                Tc[k] = s;
            }
#pragma unroll
            for (int r = 0; r < 4; r++) {
                if (r < c) {
                    float s = 0.f;
#pragma unroll
                    for (int k = 0; k < 4; k++) s = fmaf(ob[4*k+r], Tc[k], s);
                    int idx = (r == 0) ? (c - 1) : ((r == 1) ? (c + 1) : 5);
                    Eo[idx] = s * rs2;
                } else if (r == c) {
                    float s = 0.f;
#pragma unroll
                    for (int k = 0; k < 4; k++) s = fmaf(ob[4*k+r], Tc[k], s);
                    Ed[c] = s * rs;
                }
            }
        }

        // v = adjS mb; f' = -2 rs Ob^T v; h = rs (mb.v)
        float v[4], fp[4];
        float h = 0.f;
#pragma unroll
        for (int r = 0; r < 4; r++) {
            float s = 0.f;
#pragma unroll
            for (int k = 0; k < 4; k++) s = fmaf(SYM(aS, r, k), mb[k], s);
            v[r] = s;
            h = fmaf(mb[r], s, h);
        }
        float nrs2 = -2.0f * rs;
#pragma unroll
        for (int r = 0; r < 4; r++) {
            float s = 0.f;
#pragma unroll
            for (int k = 0; k < 4; k++) s = fmaf(ob[4*k+r], v[k], s);
            fp[r] = s * nrs2;
        }
        float hcb = fmaf(h, rs, cb - 4.0f);

        float4* d = (float4*)&sbuf[(m * GH_TILE + g) * SB_STRIDE];
        d[0] = make_float4(Ed[0], Ed[1], Ed[2], Ed[3]);
        d[1] = make_float4(Eo[0], Eo[1], Eo[2], Eo[3]);
        d[2] = make_float4(Eo[4], Eo[5], fp[0], fp[1]);
        d[3] = make_float4(fp[2], fp[3], hcb, 0.f);
    }
    __syncthreads();

    // ---- phase 2: two n per thread ----
    int lg = tid & 15;
    int wn = tid >> 4;          // 0..7
    int gh = gh0 + lg;
    int n1 = n0 + wn;
    int n2 = n1 + 8;
    int t1 = n1 * GH + gh;
    int t2 = n2 * GH + gh;

    APack A1, A2;
    compute_apack(mu_a, sigma_a, omega_a, t1, A1);
    compute_apack(mu_a, sigma_a, omega_a, t2, A2);
    float ch1 = 0.5f * chi[t1];
    float ch2 = 0.5f * chi[t2];

    float* out1 = out + (size_t)n1 * (MM * GH) + gh;
    float* out2 = out + (size_t)n2 * (MM * GH) + gh;
    const float* sbb = &sbuf[lg * SB_STRIDE];

#pragma unroll
    for (int m = 0; m < MM; m++) {
        const float4* s4 = (const float4*)(sbb + m * (GH_TILE * SB_STRIDE));
        float4 e0 = s4[0];
        float4 e1 = s4[1];
        float4 e2 = s4[2];
        float4 e3 = s4[3];

        float Xa1 = e3.z + A1.nca;
        float Xb1 = 0.f;
        float Xa2 = e3.z + A2.nca;
        float Xb2 = 0.f;
        Xa1 = fmaf(e0.x, A1.Cd[0], Xa1);  Xa2 = fmaf(e0.x, A2.Cd[0], Xa2);
        Xb1 = fmaf(e0.y, A1.Cd[1], Xb1);  Xb2 = fmaf(e0.y, A2.Cd[1], Xb2);
        Xa1 = fmaf(e0.z, A1.Cd[2], Xa1);  Xa2 = fmaf(e0.z, A2.Cd[2], Xa2);
        Xb1 = fmaf(e0.w, A1.Cd[3], Xb1);  Xb2 = fmaf(e0.w, A2.Cd[3], Xb2);
        Xa1 = fmaf(e1.x, A1.Co[0], Xa1);  Xa2 = fmaf(e1.x, A2.Co[0], Xa2);
        Xb1 = fmaf(e1.y, A1.Co[1], Xb1);  Xb2 = fmaf(e1.y, A2.Co[1], Xb2);
        Xa1 = fmaf(e1.z, A1.Co[2], Xa1);  Xa2 = fmaf(e1.z, A2.Co[2], Xa2);
        Xb1 = fmaf(e1.w, A1.Co[3], Xb1);  Xb2 = fmaf(e1.w, A2.Co[3], Xb2);
        Xa1 = fmaf(e2.x, A1.Co[4], Xa1);  Xa2 = fmaf(e2.x, A2.Co[4], Xa2);
        Xb1 = fmaf(e2.y, A1.Co[5], Xb1);  Xb2 = fmaf(e2.y, A2.Co[5], Xb2);
        Xa1 = fmaf(e2.z, A1.p[0], Xa1);   Xa2 = fmaf(e2.z, A2.p[0], Xa2);
        Xb1 = fmaf(e2.w, A1.p[1], Xb1);   Xb2 = fmaf(e2.w, A2.p[1], Xb2);
        Xa1 = fmaf(e3.x, A1.p[2], Xa1);   Xa2 = fmaf(e3.x, A2.p[2], Xa2);
        Xb1 = fmaf(e3.y, A1.p[3], Xb1);   Xb2 = fmaf(e3.y, A2.p[3], Xb2);

        float X1 = Xa1 + Xb1;
        float X2 = Xa2 + Xb2;

        // S = chi * sigmoid(-0.1 X) = 0.5 chi + 0.5 chi * tanh(-0.05 X)
        float th1 = fast_tanh(-0.05f * X1);
        float th2 = fast_tanh(-0.05f * X2);
        float S1 = fmaf(ch1, th1, ch1);
        float S2 = fmaf(ch2, th2, ch2);
        out1[(size_t)m * GH] = S1;
        out2[(size_t)m * GH] = S2;
    }
}

// ---------------------------------------------------------------------------
extern "C" void kernel_launch(void* const* d_in, const int* in_sizes, int n_in,
                              void* d_out, int out_size)
{
    const float* mu_a    = (const float*)d_in[0];
    const float* sigma_a = (const float*)d_in[1];
    const float* omega_a = (const float*)d_in[2];
    const float* mu_b    = (const float*)d_in[3];
    const float* sigma_b = (const float*)d_in[4];
    const float* omega_b = (const float*)d_in[5];
    const float* chi     = (const float*)d_in[6];
    float* out = (float*)d_out;

    dim3 grid(GH / GH_TILE, NN / N_TILE);   // (256, 4) = 1024 blocks
    species_fused_kernel<<<grid, NTHREADS>>>(mu_a, sigma_a, omega_a,
                                             mu_b, sigma_b, omega_b, chi, out);
}